// round 12
// baseline (speedup 1.0000x reference)
#include <cuda_runtime.h>
#include <cstdint>

#define HRR   1024
#define NDEC  16
#define OUTW  (HRR * (2 + 2 * NDEC))   // 34816 floats per row
#define ZPAD  34                       // zbuf row stride in float2 (17 float4, 272B)

typedef unsigned long long ull;        // packed complex: lo=re, hi=im

// Decoder spectra, pair-packed for LDG.128:
// g_Gw[(d*16 + j)*32 + lane] = { G[d][64j+lane], G[d][64j+32+lane] },
// where G[d][k] = conj(FFT(dec_d))[k] / 1024.
__device__ ulonglong2 g_Gw[NDEC * 16 * 32];

// ---------------- packed f32x2 primitives ----------------
static __device__ __forceinline__ ull pk(float x, float y) {
    ull r;
    asm("mov.b64 %0, {%1, %2};" : "=l"(r)
        : "r"(__float_as_uint(x)), "r"(__float_as_uint(y)));
    return r;
}
static __device__ __forceinline__ float2 unpk(ull a) {
    unsigned x, y;
    asm("mov.b64 {%0, %1}, %2;" : "=r"(x), "=r"(y) : "l"(a));
    return make_float2(__uint_as_float(x), __uint_as_float(y));
}
static __device__ __forceinline__ ull pswap(ull a) {   // {im, re}
    unsigned x, y;
    asm("mov.b64 {%0, %1}, %2;" : "=r"(x), "=r"(y) : "l"(a));
    ull r;
    asm("mov.b64 %0, {%1, %2};" : "=l"(r) : "r"(y), "r"(x));
    return r;
}
static __device__ __forceinline__ ull padd(ull a, ull b) {
    ull d; asm("add.rn.f32x2 %0, %1, %2;" : "=l"(d) : "l"(a), "l"(b)); return d;
}
static __device__ __forceinline__ ull pmul(ull a, ull b) {
    ull d; asm("mul.rn.f32x2 %0, %1, %2;" : "=l"(d) : "l"(a), "l"(b)); return d;
}
static __device__ __forceinline__ ull pfma(ull a, ull b, ull c) {
    ull d; asm("fma.rn.f32x2 %0, %1, %2, %3;" : "=l"(d) : "l"(a), "l"(b), "l"(c)); return d;
}
// a - b  (exact: fma with -1 multiplier)
static __device__ __forceinline__ ull psub(ull a, ull b, ull neg1) {
    return pfma(b, neg1, a);
}
// packed complex multiply by twiddle given wxx={wx,wx}, wmy={-wy,wy}
static __device__ __forceinline__ ull pcmulw(ull d, ull wxx, ull wmy) {
    return pfma(pswap(d), wmy, pmul(d, wxx));
}
// a * (+i): (x,y) -> (-y, x)   [swap + sign-XOR on lo; ALU pipe, no fma]
static __device__ __forceinline__ ull pmuli_p(ull a) {
    unsigned x, y;
    asm("mov.b64 {%0, %1}, %2;" : "=r"(x), "=r"(y) : "l"(a));
    unsigned nlo = y ^ 0x80000000u;
    ull r;
    asm("mov.b64 %0, {%1, %2};" : "=l"(r) : "r"(nlo), "r"(x));
    return r;
}
// a * (-i): (x,y) -> (y, -x)
static __device__ __forceinline__ ull pmuli_m(ull a) {
    unsigned x, y;
    asm("mov.b64 {%0, %1}, %2;" : "=r"(x), "=r"(y) : "l"(a));
    unsigned nhi = x ^ 0x80000000u;
    ull r;
    asm("mov.b64 %0, {%1, %2};" : "=l"(r) : "r"(y), "r"(nhi));
    return r;
}
// 128-bit shared store of two packed complexes
static __device__ __forceinline__ void sts_v2u64(float2* p, ull a, ull b) {
    unsigned addr = (unsigned)__cvta_generic_to_shared(p);
    asm volatile("st.shared.v2.u64 [%0], {%1, %2};" :: "r"(addr), "l"(a), "l"(b) : "memory");
}

static __device__ __forceinline__ float2 cmul(float2 a, float2 b) {
    return make_float2(fmaf(a.x, b.x, -a.y * b.y), fmaf(a.x, b.y, a.y * b.x));
}

// Twiddle chain state in (xx, my) representation: for t = (x, y),
// xx = {x, x}, my = {-y, y}.  Apply to data d: d*t = pswap(d)*my + d*xx.
// Chain step by w (constants wxx={wx,wx}, wmy={-wy,wy}, wmyN={wy,-wy}):
//   my' = my*wxx + xx*wmy      ( = {-(x wy + y wx), x wy + y wx} )
//   xx' = my*wmyN + xx*wxx     ( = {x wx - y wy, x wx - y wy} )
// 4 packed fma, zero movs.  Algebra verified (t=i, w=i -> t'=-1).
static __device__ __forceinline__ void pstep(ull& xx, ull& my,
                                             ull wxx, ull wmy, ull wmyN) {
    ull nmy = pfma(my, wxx,  pmul(xx, wmy));
    ull nxx = pfma(my, wmyN, pmul(xx, wxx));
    xx = nxx; my = nmy;
}
static __device__ __forceinline__ ull ptw(ull d, ull xx, ull my) {
    return pfma(pswap(d), my, pmul(d, xx));
}

// cos/sin(2*pi*t/32), t = 0..15
__device__ constexpr float C32T[16] = {
    1.0f,          0.980785280f,  0.923879533f,  0.831469612f,
    0.707106781f,  0.555570233f,  0.382683432f,  0.195090322f,
    0.0f,         -0.195090322f, -0.382683432f, -0.555570233f,
   -0.707106781f, -0.831469612f, -0.923879533f, -0.980785280f };
__device__ constexpr float S32T[16] = {
    0.0f,          0.195090322f,  0.382683432f,  0.555570233f,
    0.707106781f,  0.831469612f,  0.923879533f,  0.980785280f,
    1.0f,          0.980785280f,  0.923879533f,  0.831469612f,
    0.707106781f,  0.555570233f,  0.382683432f,  0.195090322f };

__device__ __host__ constexpr int brev5(int x) {
    return ((x & 1) << 4) | ((x & 2) << 2) | (x & 4) | ((x & 8) >> 2) | ((x & 16) >> 4);
}

// Even-XOR swizzle for the 32x32 float2 transpose buffer (index in float2
// units).  XOR with an EVEN value keeps (c, c+1) pairs adjacent and 16B
// aligned, so twiddle-apply stores are STS.128.  Conflict-free both ways
// (see R11 derivation).
static __device__ __forceinline__ int swz(int r, int c) {
    return r * 32 + (c ^ ((2 * r) & 31));
}

// One DIF radix-2 stage of an in-register 32-point FFT, packed f32x2 math.
// SGN = -1: forward (e^{-2pi i}); SGN = +1: inverse kernel (no 1/N).
template<int SGN, int M>
static __device__ __forceinline__ void fft32_stage(ull v[32], ull neg1) {
    constexpr int H = M / 2;
    constexpr int TS = 32 / M;
#pragma unroll
    for (int g = 0; g < 32; g += M) {
#pragma unroll
        for (int j = 0; j < H; j++) {
            const int t = j * TS;           // twiddle exponent, 0..15
            ull a = v[g + j], b = v[g + j + H];
            v[g + j] = padd(a, b);
            ull d = psub(a, b, neg1);
            if (t == 0) {
                v[g + j + H] = d;
            } else if (t == 8) {            // W^8 = (0, SGN): swap + sign-XOR
                v[g + j + H] = (SGN < 0) ? pmuli_m(d) : pmuli_p(d);
            } else {
                const float wc = C32T[t];
                const float ws = (SGN < 0) ? -S32T[t] : S32T[t];
                v[g + j + H] = pcmulw(d, pk(wc, wc), pk(-ws, ws));
            }
        }
    }
}

template<int SGN>
static __device__ __forceinline__ void fft32(ull v[32]) {
    const ull neg1 = pk(-1.0f, -1.0f);
    fft32_stage<SGN, 32>(v, neg1);
    fft32_stage<SGN, 16>(v, neg1);
    fft32_stage<SGN, 8>(v, neg1);
    fft32_stage<SGN, 4>(v, neg1);
    fft32_stage<SGN, 2>(v, neg1);
}

// Warp-level 1024-point complex FFT (four-step, 32 lanes x 32 packed regs).
// Input:  v[a] on lane b = x[32*a + b]   (natural order)
// Output: v[r] on lane c = X[c + 32*brev5(r)]
// Twiddles W_1024^{SGN*lane*c} via FOUR independent packed chains in
// (xx, my) representation (A: c=0..7, B: 8..15, C: 16..23, D: 24..31);
// fully packed math, stores as st.shared.v2.u64.
template<int SGN>
static __device__ __forceinline__ void warp_fft1024(ull (&v)[32], int lane, float2* tb) {
    fft32<SGN>(v);   // per-lane FFT over a -> frequency index c (bit-reversed in regs)

    const float ang = (float)SGN * (6.283185307179586f / 1024.0f) * (float)lane;
    float s1, c1, s8, c8, s16, c16;
    __sincosf(ang, &s1, &c1);
    __sincosf(8.0f * ang, &s8, &c8);
    __sincosf(16.0f * ang, &s16, &c16);
    // step constants for w = (c1, s1)
    const ull wxx  = pk(c1, c1);
    const ull wmy  = pk(-s1, s1);
    const ull wmyN = pk(s1, -s1);
    // chain states: A = W^0, B = W^{8l}, C = W^{16l}, D = W^{24l}
    ull Axx = pk(1.0f, 1.0f), Amy = pk(0.0f, 0.0f);
    ull Bxx = pk(c8, c8),     Bmy = pk(-s8, s8);
    ull Cxx = pk(c16, c16),   Cmy = pk(-s16, s16);
    float2 d24 = cmul(make_float2(c8, s8), make_float2(c16, s16));
    ull Dxx = pk(d24.x, d24.x), Dmy = pk(-d24.y, d24.y);

#pragma unroll
    for (int m = 0; m < 4; m++) {
        const int cA = 2 * m, cB = cA + 8, cC = cA + 16, cD = cA + 24;
        ull a0 = ptw(v[brev5(cA)],     Axx, Amy); pstep(Axx, Amy, wxx, wmy, wmyN);
        ull b0 = ptw(v[brev5(cB)],     Bxx, Bmy); pstep(Bxx, Bmy, wxx, wmy, wmyN);
        ull q0 = ptw(v[brev5(cC)],     Cxx, Cmy); pstep(Cxx, Cmy, wxx, wmy, wmyN);
        ull d0 = ptw(v[brev5(cD)],     Dxx, Dmy); pstep(Dxx, Dmy, wxx, wmy, wmyN);
        ull a1 = ptw(v[brev5(cA + 1)], Axx, Amy); pstep(Axx, Amy, wxx, wmy, wmyN);
        ull b1 = ptw(v[brev5(cB + 1)], Bxx, Bmy); pstep(Bxx, Bmy, wxx, wmy, wmyN);
        ull q1 = ptw(v[brev5(cC + 1)], Cxx, Cmy); pstep(Cxx, Cmy, wxx, wmy, wmyN);
        ull d1 = ptw(v[brev5(cD + 1)], Dxx, Dmy); pstep(Dxx, Dmy, wxx, wmy, wmyN);
        sts_v2u64(&tb[swz(lane, cA)], a0, a1);
        sts_v2u64(&tb[swz(lane, cB)], b0, b1);
        sts_v2u64(&tb[swz(lane, cC)], q0, q1);
        sts_v2u64(&tb[swz(lane, cD)], d0, d1);
    }
    __syncwarp();
#pragma unroll
    for (int b = 0; b < 32; b++)
        v[b] = *(const ull*)&tb[swz(b, lane)];   // ld.shared.b64, lane holds fixed c
    __syncwarp();   // protect tb before caller's next use

    fft32<SGN>(v);   // FFT over b -> index d (bit-reversed in regs)
}

// ---------------------------------------------------------------------------
// Kernel 1: decoder spectra. One block (1 warp) per decoder.
__global__ __launch_bounds__(32)
void hrr_prep_kernel(const float* __restrict__ dec) {
    __shared__ alignas(16) float2 tb[32 * 32];
    const int lane = threadIdx.x;
    const int d = blockIdx.x;
    ull v[32];
#pragma unroll
    for (int a = 0; a < 32; a++)
        v[a] = pk(__ldg(&dec[d * HRR + 32 * a + lane]), 0.0f);
    warp_fft1024<-1>(v, lane, tb);
    const float inv = 1.0f / 1024.0f;
#pragma unroll
    for (int r = 0; r < 32; r++) {
        int m = brev5(r);                       // k = lane + 32*m
        float2 s = unpk(v[r]);
        ull val = pk(s.x * inv, -s.y * inv);    // conj / N
        ((ull*)g_Gw)[((d * 16 + (m >> 1)) * 32 + lane) * 2 + (m & 1)] = val;
    }
}

// ---------------------------------------------------------------------------
// Kernel 2: one CTA (4 warps) per batch row.
//   z = p + i*l; Z = FFT(z); for each decoder d: y = IFFT(G_d * Z);
//   Re(y) -> assoc_p[d], Im(y) -> assoc_l[d].
__global__ __launch_bounds__(128)
void hrr_main_kernel(const float* __restrict__ P,
                     const float* __restrict__ L,
                     float* __restrict__ out) {
    // Z spectrum, lane-transposed: zbuf[lane*ZPAD + a] = Z[32a + lane].
    __shared__ alignas(16) float2 zbuf[32 * ZPAD];
    __shared__ alignas(16) float2 tb[4][32 * 32];

    const int b    = blockIdx.x;
    const int tid  = threadIdx.x;
    const int wid  = tid >> 5;
    const int lane = tid & 31;

    const float* pr = P + (size_t)b * HRR;
    const float* lr = L + (size_t)b * HRR;
    float* outr = out + (size_t)b * OUTW;

    ull v[32];

    if (wid == 0) {
        // Warp 0: forward FFT of z = p + i*l (runs concurrently with the copy)
#pragma unroll
        for (int a = 0; a < 32; a++)
            v[a] = pk(__ldg(&pr[32 * a + lane]), __ldg(&lr[32 * a + lane]));
        warp_fft1024<-1>(v, lane, tb[0]);
#pragma unroll
        for (int r = 0; r < 32; r++)
            *(ull*)&zbuf[lane * ZPAD + brev5(r)] = v[r];
    } else {
        // Warps 1-3: copy p, l rows into out[0:2048) (vectorized, streaming)
        const float4* p4 = (const float4*)pr;
        const float4* l4 = (const float4*)lr;
        float4* o4 = (float4*)outr;
        for (int i = tid - 32; i < HRR / 4; i += 96) {
            __stcs(&o4[i],           __ldg(&p4[i]));
            __stcs(&o4[HRR / 4 + i], __ldg(&l4[i]));
        }
    }
    __syncthreads();

    // 16 inverse FFTs, 4 per warp. Per FFT: 16 LDS.128 (zbuf) + 16 LDG.128 (G).
    const float4* z4 = (const float4*)(zbuf + lane * ZPAD);
#pragma unroll 1
    for (int d = wid; d < NDEC; d += 4) {
        const ulonglong2* Gw = g_Gw + (size_t)d * 16 * 32;
#pragma unroll
        for (int j = 0; j < 16; j++) {
            float4 zz = z4[j];                                  // a = 2j, 2j+1
            ulonglong2 g = __ldg(&Gw[j * 32 + lane]);
            float2 r0 = cmul(make_float2(zz.x, zz.y), unpk(g.x));
            float2 r1 = cmul(make_float2(zz.z, zz.w), unpk(g.y));
            v[2 * j]     = pk(r0.x, r0.y);
            v[2 * j + 1] = pk(r1.x, r1.y);
        }
        warp_fft1024<1>(v, lane, tb[wid]);

        float* op = outr + 2 * HRR + d * HRR;                // assoc_p block
        float* ol = outr + 2 * HRR + NDEC * HRR + d * HRR;   // assoc_l block
#pragma unroll
        for (int r = 0; r < 32; r++) {
            int k = lane + 32 * brev5(r);
            float2 s = unpk(v[r]);
            __stcs(&op[k], s.x);
            __stcs(&ol[k], s.y);
        }
    }
}

// ---------------------------------------------------------------------------
extern "C" void kernel_launch(void* const* d_in, const int* in_sizes, int n_in,
                              void* d_out, int out_size) {
    // metadata order: problemhrr [B,1024], lemmahrr [B,1024], decoders [16,1024]
    const float* P = (const float*)d_in[0];
    const float* L = (const float*)d_in[1];
    const float* D = (const float*)d_in[2];
    // defensive: identify the decoders tensor by its unique size
    if (in_sizes[0] == NDEC * HRR) {
        D = (const float*)d_in[0]; P = (const float*)d_in[1]; L = (const float*)d_in[2];
    } else if (in_sizes[1] == NDEC * HRR) {
        P = (const float*)d_in[0]; D = (const float*)d_in[1]; L = (const float*)d_in[2];
    }
    const int B = out_size / OUTW;

    hrr_prep_kernel<<<NDEC, 32>>>(D);
    hrr_main_kernel<<<B, 128>>>(P, L, (float*)d_out);
}

// round 13
// speedup vs baseline: 1.0041x; 1.0041x over previous
#include <cuda_runtime.h>
#include <cstdint>

#define HRR   1024
#define NDEC  16
#define OUTW  (HRR * (2 + 2 * NDEC))   // 34816 floats per row
#define ZPAD  34                       // zbuf row stride in float2 (17 float4, 272B)

typedef unsigned long long ull;        // packed complex: lo=re, hi=im

// Decoder spectra, pair-packed for LDG.128:
// g_Gw[(d*16 + j)*32 + lane] = { G[d][64j+lane], G[d][64j+32+lane] },
// where G[d][k] = conj(FFT(dec_d))[k] / 1024.
__device__ ulonglong2 g_Gw[NDEC * 16 * 32];

// ---------------- packed f32x2 primitives ----------------
static __device__ __forceinline__ ull pk(float x, float y) {
    ull r;
    asm("mov.b64 %0, {%1, %2};" : "=l"(r)
        : "r"(__float_as_uint(x)), "r"(__float_as_uint(y)));
    return r;
}
static __device__ __forceinline__ float2 unpk(ull a) {
    unsigned x, y;
    asm("mov.b64 {%0, %1}, %2;" : "=r"(x), "=r"(y) : "l"(a));
    return make_float2(__uint_as_float(x), __uint_as_float(y));
}
static __device__ __forceinline__ ull pswap(ull a) {   // {im, re}
    unsigned x, y;
    asm("mov.b64 {%0, %1}, %2;" : "=r"(x), "=r"(y) : "l"(a));
    ull r;
    asm("mov.b64 %0, {%1, %2};" : "=l"(r) : "r"(y), "r"(x));
    return r;
}
static __device__ __forceinline__ ull padd(ull a, ull b) {
    ull d; asm("add.rn.f32x2 %0, %1, %2;" : "=l"(d) : "l"(a), "l"(b)); return d;
}
static __device__ __forceinline__ ull pmul(ull a, ull b) {
    ull d; asm("mul.rn.f32x2 %0, %1, %2;" : "=l"(d) : "l"(a), "l"(b)); return d;
}
static __device__ __forceinline__ ull pfma(ull a, ull b, ull c) {
    ull d; asm("fma.rn.f32x2 %0, %1, %2, %3;" : "=l"(d) : "l"(a), "l"(b), "l"(c)); return d;
}
// a - b  (exact: fma with -1 multiplier)
static __device__ __forceinline__ ull psub(ull a, ull b, ull neg1) {
    return pfma(b, neg1, a);
}
// packed complex multiply by twiddle given wxx={wx,wx}, wmy={-wy,wy}
static __device__ __forceinline__ ull pcmulw(ull d, ull wxx, ull wmy) {
    return pfma(pswap(d), wmy, pmul(d, wxx));
}
// a * (+i): (x,y) -> (-y, x)   [swap + sign-XOR; ALU pipe, no fma]
static __device__ __forceinline__ ull pmuli_p(ull a) {
    unsigned x, y;
    asm("mov.b64 {%0, %1}, %2;" : "=r"(x), "=r"(y) : "l"(a));
    unsigned nlo = y ^ 0x80000000u;
    ull r;
    asm("mov.b64 %0, {%1, %2};" : "=l"(r) : "r"(nlo), "r"(x));
    return r;
}
// a * (-i): (x,y) -> (y, -x)
static __device__ __forceinline__ ull pmuli_m(ull a) {
    unsigned x, y;
    asm("mov.b64 {%0, %1}, %2;" : "=r"(x), "=r"(y) : "l"(a));
    unsigned nhi = x ^ 0x80000000u;
    ull r;
    asm("mov.b64 %0, {%1, %2};" : "=l"(r) : "r"(y), "r"(nhi));
    return r;
}
// 128-bit shared store of two packed complexes
static __device__ __forceinline__ void sts_v2u64(float2* p, ull a, ull b) {
    unsigned addr = (unsigned)__cvta_generic_to_shared(p);
    asm volatile("st.shared.v2.u64 [%0], {%1, %2};" :: "r"(addr), "l"(a), "l"(b) : "memory");
}
// L2 prefetch (no register writeback, no scoreboard)
static __device__ __forceinline__ void pref_l2(const void* p) {
    asm volatile("prefetch.global.L2 [%0];" :: "l"(p));
}

static __device__ __forceinline__ float2 cmul(float2 a, float2 b) {
    return make_float2(fmaf(a.x, b.x, -a.y * b.y), fmaf(a.x, b.y, a.y * b.x));
}

// cos/sin(2*pi*t/32), t = 0..15
__device__ constexpr float C32T[16] = {
    1.0f,          0.980785280f,  0.923879533f,  0.831469612f,
    0.707106781f,  0.555570233f,  0.382683432f,  0.195090322f,
    0.0f,         -0.195090322f, -0.382683432f, -0.555570233f,
   -0.707106781f, -0.831469612f, -0.923879533f, -0.980785280f };
__device__ constexpr float S32T[16] = {
    0.0f,          0.195090322f,  0.382683432f,  0.555570233f,
    0.707106781f,  0.831469612f,  0.923879533f,  0.980785280f,
    1.0f,          0.980785280f,  0.923879533f,  0.831469612f,
    0.707106781f,  0.555570233f,  0.382683432f,  0.195090322f };

__device__ __host__ constexpr int brev5(int x) {
    return ((x & 1) << 4) | ((x & 2) << 2) | (x & 4) | ((x & 8) >> 2) | ((x & 16) >> 4);
}

// Even-XOR swizzle for the 32x32 float2 transpose buffer (index in float2
// units).  XOR with an EVEN value keeps (c, c+1) pairs adjacent and 16B
// aligned, so twiddle-apply stores are STS.128.  Conflict-free both ways
// (see R11 derivation).
static __device__ __forceinline__ int swz(int r, int c) {
    return r * 32 + (c ^ ((2 * r) & 31));
}

// One DIF radix-2 stage of an in-register 32-point FFT, packed f32x2 math.
// SGN = -1: forward (e^{-2pi i}); SGN = +1: inverse kernel (no 1/N).
template<int SGN, int M>
static __device__ __forceinline__ void fft32_stage(ull v[32], ull neg1) {
    constexpr int H = M / 2;
    constexpr int TS = 32 / M;
#pragma unroll
    for (int g = 0; g < 32; g += M) {
#pragma unroll
        for (int j = 0; j < H; j++) {
            const int t = j * TS;           // twiddle exponent, 0..15
            ull a = v[g + j], b = v[g + j + H];
            v[g + j] = padd(a, b);
            ull d = psub(a, b, neg1);
            if (t == 0) {
                v[g + j + H] = d;
            } else if (t == 8) {            // W^8 = (0, SGN): swap + sign-XOR
                v[g + j + H] = (SGN < 0) ? pmuli_m(d) : pmuli_p(d);
            } else {
                const float wc = C32T[t];
                const float ws = (SGN < 0) ? -S32T[t] : S32T[t];
                v[g + j + H] = pcmulw(d, pk(wc, wc), pk(-ws, ws));
            }
        }
    }
}

template<int SGN>
static __device__ __forceinline__ void fft32(ull v[32]) {
    const ull neg1 = pk(-1.0f, -1.0f);
    fft32_stage<SGN, 32>(v, neg1);
    fft32_stage<SGN, 16>(v, neg1);
    fft32_stage<SGN, 8>(v, neg1);
    fft32_stage<SGN, 4>(v, neg1);
    fft32_stage<SGN, 2>(v, neg1);
}

// Warp-level 1024-point complex FFT (four-step, 32 lanes x 32 packed regs).
// Input:  v[a] on lane b = x[32*a + b]   (natural order)
// Output: v[r] on lane c = X[c + 32*brev5(r)]
// Twiddles W_1024^{SGN*lane*c} via FOUR independent scalar float2 chains
// (A: c=0..7, B: 8..15, C: 16..23, D: 24..31), two dependent steps per
// pair-iteration; pair results stored via st.shared.v2.u64.
template<int SGN>
static __device__ __forceinline__ void warp_fft1024(ull (&v)[32], int lane, float2* tb) {
    fft32<SGN>(v);   // per-lane FFT over a -> frequency index c (bit-reversed in regs)

    const float ang = (float)SGN * (6.283185307179586f / 1024.0f) * (float)lane;
    float s1, c1, s8, c8, s16, c16;
    __sincosf(ang, &s1, &c1);
    __sincosf(8.0f * ang, &s8, &c8);
    __sincosf(16.0f * ang, &s16, &c16);
    const float2 w = make_float2(c1, s1);
    float2 tA = make_float2(1.0f, 0.0f);
    float2 tB = make_float2(c8, s8);
    float2 tC = make_float2(c16, s16);
    float2 tD = cmul(tB, tC);
#pragma unroll
    for (int m = 0; m < 4; m++) {
        const int cA = 2 * m, cB = cA + 8, cC = cA + 16, cD = cA + 24;
        float2 a0 = cmul(unpk(v[brev5(cA)]),     tA);
        float2 b0 = cmul(unpk(v[brev5(cB)]),     tB);
        float2 q0 = cmul(unpk(v[brev5(cC)]),     tC);
        float2 d0 = cmul(unpk(v[brev5(cD)]),     tD);
        tA = cmul(tA, w); tB = cmul(tB, w); tC = cmul(tC, w); tD = cmul(tD, w);
        float2 a1 = cmul(unpk(v[brev5(cA + 1)]), tA);
        float2 b1 = cmul(unpk(v[brev5(cB + 1)]), tB);
        float2 q1 = cmul(unpk(v[brev5(cC + 1)]), tC);
        float2 d1 = cmul(unpk(v[brev5(cD + 1)]), tD);
        tA = cmul(tA, w); tB = cmul(tB, w); tC = cmul(tC, w); tD = cmul(tD, w);
        sts_v2u64(&tb[swz(lane, cA)], pk(a0.x, a0.y), pk(a1.x, a1.y));
        sts_v2u64(&tb[swz(lane, cB)], pk(b0.x, b0.y), pk(b1.x, b1.y));
        sts_v2u64(&tb[swz(lane, cC)], pk(q0.x, q0.y), pk(q1.x, q1.y));
        sts_v2u64(&tb[swz(lane, cD)], pk(d0.x, d0.y), pk(d1.x, d1.y));
    }
    __syncwarp();
#pragma unroll
    for (int b = 0; b < 32; b++)
        v[b] = *(const ull*)&tb[swz(b, lane)];   // ld.shared.b64, lane holds fixed c
    __syncwarp();   // protect tb before caller's next use

    fft32<SGN>(v);   // FFT over b -> index d (bit-reversed in regs)
}

// ---------------------------------------------------------------------------
// Kernel 1: decoder spectra. One block (1 warp) per decoder.
__global__ __launch_bounds__(32)
void hrr_prep_kernel(const float* __restrict__ dec) {
    __shared__ alignas(16) float2 tb[32 * 32];
    const int lane = threadIdx.x;
    const int d = blockIdx.x;
    ull v[32];
#pragma unroll
    for (int a = 0; a < 32; a++)
        v[a] = pk(__ldg(&dec[d * HRR + 32 * a + lane]), 0.0f);
    warp_fft1024<-1>(v, lane, tb);
    const float inv = 1.0f / 1024.0f;
#pragma unroll
    for (int r = 0; r < 32; r++) {
        int m = brev5(r);                       // k = lane + 32*m
        float2 s = unpk(v[r]);
        ull val = pk(s.x * inv, -s.y * inv);    // conj / N
        ((ull*)g_Gw)[((d * 16 + (m >> 1)) * 32 + lane) * 2 + (m & 1)] = val;
    }
}

// ---------------------------------------------------------------------------
// Kernel 2: one CTA (4 warps) per batch row.
//   z = p + i*l; Z = FFT(z); for each decoder d: y = IFFT(G_d * Z);
//   Re(y) -> assoc_p[d], Im(y) -> assoc_l[d].
__global__ __launch_bounds__(128)
void hrr_main_kernel(const float* __restrict__ P,
                     const float* __restrict__ L,
                     float* __restrict__ out) {
    // Z spectrum, lane-transposed: zbuf[lane*ZPAD + a] = Z[32a + lane].
    __shared__ alignas(16) float2 zbuf[32 * ZPAD];
    __shared__ alignas(16) float2 tb[4][32 * 32];

    const int b    = blockIdx.x;
    const int tid  = threadIdx.x;
    const int wid  = tid >> 5;
    const int lane = tid & 31;

    const float* pr = P + (size_t)b * HRR;
    const float* lr = L + (size_t)b * HRR;
    float* outr = out + (size_t)b * OUTW;

    ull v[32];

    if (wid == 0) {
        // Warp 0: forward FFT of z = p + i*l (runs concurrently with the copy)
#pragma unroll
        for (int a = 0; a < 32; a++)
            v[a] = pk(__ldg(&pr[32 * a + lane]), __ldg(&lr[32 * a + lane]));
        warp_fft1024<-1>(v, lane, tb[0]);
#pragma unroll
        for (int r = 0; r < 32; r++)
            *(ull*)&zbuf[lane * ZPAD + brev5(r)] = v[r];
    } else {
        // Warps 1-3: copy p, l rows into out[0:2048) (vectorized, streaming)
        const float4* p4 = (const float4*)pr;
        const float4* l4 = (const float4*)lr;
        float4* o4 = (float4*)outr;
        for (int i = tid - 32; i < HRR / 4; i += 96) {
            __stcs(&o4[i],           __ldg(&p4[i]));
            __stcs(&o4[HRR / 4 + i], __ldg(&l4[i]));
        }
    }
    // Warm L2 with this warp's first G tile while waiting at the barrier
    {
        const char* g0 = (const char*)(g_Gw + (size_t)wid * 16 * 32);
        pref_l2(g0 + lane * 128);
        pref_l2(g0 + 4096 + lane * 128);
    }
    __syncthreads();

    // 16 inverse FFTs, 4 per warp. Per FFT: 16 LDS.128 (zbuf) + 16 LDG.128 (G).
    const float4* z4 = (const float4*)(zbuf + lane * ZPAD);
#pragma unroll 1
    for (int d = wid; d < NDEC; d += 4) {
        // Prefetch next decoder's G tile (8KB = 64 lines; 2 lines per lane)
        if (d + 4 < NDEC) {
            const char* gn = (const char*)(g_Gw + (size_t)(d + 4) * 16 * 32);
            pref_l2(gn + lane * 128);
            pref_l2(gn + 4096 + lane * 128);
        }
        const ulonglong2* Gw = g_Gw + (size_t)d * 16 * 32;
#pragma unroll
        for (int j = 0; j < 16; j++) {
            float4 zz = z4[j];                                  // a = 2j, 2j+1
            ulonglong2 g = __ldg(&Gw[j * 32 + lane]);
            float2 r0 = cmul(make_float2(zz.x, zz.y), unpk(g.x));
            float2 r1 = cmul(make_float2(zz.z, zz.w), unpk(g.y));
            v[2 * j]     = pk(r0.x, r0.y);
            v[2 * j + 1] = pk(r1.x, r1.y);
        }
        warp_fft1024<1>(v, lane, tb[wid]);

        float* op = outr + 2 * HRR + d * HRR;                // assoc_p block
        float* ol = outr + 2 * HRR + NDEC * HRR + d * HRR;   // assoc_l block
#pragma unroll
        for (int r = 0; r < 32; r++) {
            int k = lane + 32 * brev5(r);
            float2 s = unpk(v[r]);
            __stcs(&op[k], s.x);
            __stcs(&ol[k], s.y);
        }
    }
}

// ---------------------------------------------------------------------------
extern "C" void kernel_launch(void* const* d_in, const int* in_sizes, int n_in,
                              void* d_out, int out_size) {
    // metadata order: problemhrr [B,1024], lemmahrr [B,1024], decoders [16,1024]
    const float* P = (const float*)d_in[0];
    const float* L = (const float*)d_in[1];
    const float* D = (const float*)d_in[2];
    // defensive: identify the decoders tensor by its unique size
    if (in_sizes[0] == NDEC * HRR) {
        D = (const float*)d_in[0]; P = (const float*)d_in[1]; L = (const float*)d_in[2];
    } else if (in_sizes[1] == NDEC * HRR) {
        P = (const float*)d_in[0]; D = (const float*)d_in[1]; L = (const float*)d_in[2];
    }
    const int B = out_size / OUTW;

    hrr_prep_kernel<<<NDEC, 32>>>(D);
    hrr_main_kernel<<<B, 128>>>(P, L, (float*)d_out);
}

// round 15
// speedup vs baseline: 1.0521x; 1.0478x over previous
#include <cuda_runtime.h>
#include <cstdint>

#define HRR   1024
#define NDEC  16
#define OUTW  (HRR * (2 + 2 * NDEC))   // 34816 floats per row
#define ZPAD  34                       // zbuf row stride in float2 (17 float4, 272B)

typedef unsigned long long ull;        // packed complex: lo=re, hi=im

// Decoder spectra, pair-packed for LDG.128:
// g_Gw[(d*16 + j)*32 + lane] = { G[d][64j+lane], G[d][64j+32+lane] },
// where G[d][k] = conj(FFT(dec_d))[k] / 1024.
__device__ ulonglong2 g_Gw[NDEC * 16 * 32];

// ---------------- packed f32x2 primitives ----------------
static __device__ __forceinline__ ull pk(float x, float y) {
    ull r;
    asm("mov.b64 %0, {%1, %2};" : "=l"(r)
        : "r"(__float_as_uint(x)), "r"(__float_as_uint(y)));
    return r;
}
static __device__ __forceinline__ float2 unpk(ull a) {
    unsigned x, y;
    asm("mov.b64 {%0, %1}, %2;" : "=r"(x), "=r"(y) : "l"(a));
    return make_float2(__uint_as_float(x), __uint_as_float(y));
}
static __device__ __forceinline__ ull pswap(ull a) {   // {im, re}
    unsigned x, y;
    asm("mov.b64 {%0, %1}, %2;" : "=r"(x), "=r"(y) : "l"(a));
    ull r;
    asm("mov.b64 %0, {%1, %2};" : "=l"(r) : "r"(y), "r"(x));
    return r;
}
static __device__ __forceinline__ ull padd(ull a, ull b) {
    ull d; asm("add.rn.f32x2 %0, %1, %2;" : "=l"(d) : "l"(a), "l"(b)); return d;
}
static __device__ __forceinline__ ull pmul(ull a, ull b) {
    ull d; asm("mul.rn.f32x2 %0, %1, %2;" : "=l"(d) : "l"(a), "l"(b)); return d;
}
static __device__ __forceinline__ ull pfma(ull a, ull b, ull c) {
    ull d; asm("fma.rn.f32x2 %0, %1, %2, %3;" : "=l"(d) : "l"(a), "l"(b), "l"(c)); return d;
}
// a - b  (exact: fma with -1 multiplier)
static __device__ __forceinline__ ull psub(ull a, ull b, ull neg1) {
    return pfma(b, neg1, a);
}
// packed complex multiply by twiddle given wxx={wx,wx}, wmy={-wy,wy}
static __device__ __forceinline__ ull pcmulw(ull d, ull wxx, ull wmy) {
    return pfma(pswap(d), wmy, pmul(d, wxx));
}
// a * (+i): (x,y) -> (-y, x)   [swap + sign-XOR; ALU pipe, no fma]
static __device__ __forceinline__ ull pmuli_p(ull a) {
    unsigned x, y;
    asm("mov.b64 {%0, %1}, %2;" : "=r"(x), "=r"(y) : "l"(a));
    unsigned nlo = y ^ 0x80000000u;
    ull r;
    asm("mov.b64 %0, {%1, %2};" : "=l"(r) : "r"(nlo), "r"(x));
    return r;
}
// a * (-i): (x,y) -> (y, -x)
static __device__ __forceinline__ ull pmuli_m(ull a) {
    unsigned x, y;
    asm("mov.b64 {%0, %1}, %2;" : "=r"(x), "=r"(y) : "l"(a));
    unsigned nhi = x ^ 0x80000000u;
    ull r;
    asm("mov.b64 %0, {%1, %2};" : "=l"(r) : "r"(y), "r"(nhi));
    return r;
}

static __device__ __forceinline__ float2 cmul(float2 a, float2 b) {
    return make_float2(fmaf(a.x, b.x, -a.y * b.y), fmaf(a.x, b.y, a.y * b.x));
}

// ---------------- bulk async store primitives (TMA path) ----------------
static __device__ __forceinline__ void bulk_wait0() {
    asm volatile("cp.async.bulk.wait_group 0;" ::: "memory");
}
static __device__ __forceinline__ void bulk_store4k(void* g, unsigned smem_addr) {
    asm volatile("cp.async.bulk.global.shared::cta.bulk_group [%0], [%1], 4096;"
                 :: "l"(g), "r"(smem_addr) : "memory");
}
static __device__ __forceinline__ void bulk_commit() {
    asm volatile("cp.async.bulk.commit_group;" ::: "memory");
}
static __device__ __forceinline__ void fence_async() {
    asm volatile("fence.proxy.async.shared::cta;" ::: "memory");
}

// cos/sin(2*pi*t/32), t = 0..15
__device__ constexpr float C32T[16] = {
    1.0f,          0.980785280f,  0.923879533f,  0.831469612f,
    0.707106781f,  0.555570233f,  0.382683432f,  0.195090322f,
    0.0f,         -0.195090322f, -0.382683432f, -0.555570233f,
   -0.707106781f, -0.831469612f, -0.923879533f, -0.980785280f };
__device__ constexpr float S32T[16] = {
    0.0f,          0.195090322f,  0.382683432f,  0.555570233f,
    0.707106781f,  0.831469612f,  0.923879533f,  0.980785280f,
    1.0f,          0.980785280f,  0.923879533f,  0.831469612f,
    0.707106781f,  0.555570233f,  0.382683432f,  0.195090322f };

__device__ __host__ constexpr int brev5(int x) {
    return ((x & 1) << 4) | ((x & 2) << 2) | (x & 4) | ((x & 8) >> 2) | ((x & 16) >> 4);
}

// Even-XOR swizzle for the 32x32 float2 transpose buffer (index in float2
// units).  Keeps (c, c+1) pairs adjacent and 16B aligned -> STS.128 stores.
// Conflict-free both directions (see R11 derivation).
static __device__ __forceinline__ int swz(int r, int c) {
    return r * 32 + (c ^ ((2 * r) & 31));
}

// One DIF radix-2 stage of an in-register 32-point FFT, packed f32x2 math.
// SGN = -1: forward (e^{-2pi i}); SGN = +1: inverse kernel (no 1/N).
template<int SGN, int M>
static __device__ __forceinline__ void fft32_stage(ull v[32], ull neg1) {
    constexpr int H = M / 2;
    constexpr int TS = 32 / M;
#pragma unroll
    for (int g = 0; g < 32; g += M) {
#pragma unroll
        for (int j = 0; j < H; j++) {
            const int t = j * TS;           // twiddle exponent, 0..15
            ull a = v[g + j], b = v[g + j + H];
            v[g + j] = padd(a, b);
            ull d = psub(a, b, neg1);
            if (t == 0) {
                v[g + j + H] = d;
            } else if (t == 8) {            // W^8 = (0, SGN): swap + sign-XOR
                v[g + j + H] = (SGN < 0) ? pmuli_m(d) : pmuli_p(d);
            } else {
                const float wc = C32T[t];
                const float ws = (SGN < 0) ? -S32T[t] : S32T[t];
                v[g + j + H] = pcmulw(d, pk(wc, wc), pk(-ws, ws));
            }
        }
    }
}

template<int SGN>
static __device__ __forceinline__ void fft32(ull v[32]) {
    const ull neg1 = pk(-1.0f, -1.0f);
    fft32_stage<SGN, 32>(v, neg1);
    fft32_stage<SGN, 16>(v, neg1);
    fft32_stage<SGN, 8>(v, neg1);
    fft32_stage<SGN, 4>(v, neg1);
    fft32_stage<SGN, 2>(v, neg1);
}

// Warp-level 1024-point complex FFT (four-step, 32 lanes x 32 packed regs).
// Input:  v[a] on lane b = x[32*a + b]   (natural order)
// Output: v[r] on lane c = X[c + 32*brev5(r)]
// WAIT: drain this warp's pending bulk-store group (which reads tb) right
// before the transpose stores overwrite tb; placed after fft32 #1 so the
// drain overlaps ~600 cycles of load/compute.
template<int SGN, bool WAIT>
static __device__ __forceinline__ void warp_fft1024(ull (&v)[32], int lane, float2* tb) {
    fft32<SGN>(v);   // per-lane FFT over a -> frequency index c (bit-reversed in regs)

    if (WAIT) {
        if (lane == 0) bulk_wait0();
        __syncwarp();
    }

    const float ang = (float)SGN * (6.283185307179586f / 1024.0f) * (float)lane;
    float s1, c1, s8, c8, s16, c16;
    __sincosf(ang, &s1, &c1);
    __sincosf(8.0f * ang, &s8, &c8);
    __sincosf(16.0f * ang, &s16, &c16);
    const float2 w = make_float2(c1, s1);
    float2 tA = make_float2(1.0f, 0.0f);
    float2 tB = make_float2(c8, s8);
    float2 tC = make_float2(c16, s16);
    float2 tD = cmul(tB, tC);
#pragma unroll
    for (int m = 0; m < 4; m++) {
        const int cA = 2 * m, cB = cA + 8, cC = cA + 16, cD = cA + 24;
        float2 a0 = cmul(unpk(v[brev5(cA)]),     tA);
        float2 b0 = cmul(unpk(v[brev5(cB)]),     tB);
        float2 q0 = cmul(unpk(v[brev5(cC)]),     tC);
        float2 d0 = cmul(unpk(v[brev5(cD)]),     tD);
        tA = cmul(tA, w); tB = cmul(tB, w); tC = cmul(tC, w); tD = cmul(tD, w);
        float2 a1 = cmul(unpk(v[brev5(cA + 1)]), tA);
        float2 b1 = cmul(unpk(v[brev5(cB + 1)]), tB);
        float2 q1 = cmul(unpk(v[brev5(cC + 1)]), tC);
        float2 d1 = cmul(unpk(v[brev5(cD + 1)]), tD);
        tA = cmul(tA, w); tB = cmul(tB, w); tC = cmul(tC, w); tD = cmul(tD, w);
        *(float4*)&tb[swz(lane, cA)] = make_float4(a0.x, a0.y, a1.x, a1.y);
        *(float4*)&tb[swz(lane, cB)] = make_float4(b0.x, b0.y, b1.x, b1.y);
        *(float4*)&tb[swz(lane, cC)] = make_float4(q0.x, q0.y, q1.x, q1.y);
        *(float4*)&tb[swz(lane, cD)] = make_float4(d0.x, d0.y, d1.x, d1.y);
    }
    __syncwarp();
#pragma unroll
    for (int b = 0; b < 32; b++)
        v[b] = *(const ull*)&tb[swz(b, lane)];   // ld.shared.b64, lane holds fixed c
    __syncwarp();   // tb free for reuse after this point

    fft32<SGN>(v);   // FFT over b -> index d (bit-reversed in regs)
}

// ---------------------------------------------------------------------------
// Kernel 1: decoder spectra. One block (1 warp) per decoder.
__global__ __launch_bounds__(32)
void hrr_prep_kernel(const float* __restrict__ dec) {
    __shared__ alignas(16) float2 tb[32 * 32];
    const int lane = threadIdx.x;
    const int d = blockIdx.x;
    ull v[32];
#pragma unroll
    for (int a = 0; a < 32; a++)
        v[a] = pk(__ldg(&dec[d * HRR + 32 * a + lane]), 0.0f);
    warp_fft1024<-1, false>(v, lane, tb);
    const float inv = 1.0f / 1024.0f;
#pragma unroll
    for (int r = 0; r < 32; r++) {
        int m = brev5(r);                       // k = lane + 32*m
        float2 s = unpk(v[r]);
        ull val = pk(s.x * inv, -s.y * inv);    // conj / N
        ((ull*)g_Gw)[((d * 16 + (m >> 1)) * 32 + lane) * 2 + (m & 1)] = val;
    }
}

// ---------------------------------------------------------------------------
// Kernel 2: one CTA (4 warps) per batch row.
//   z = p + i*l; Z = FFT(z); for each decoder d: y = IFFT(G_d * Z);
//   Re(y) -> assoc_p[d], Im(y) -> assoc_l[d]  via TMA bulk stores.
__global__ __launch_bounds__(128)
void hrr_main_kernel(const float* __restrict__ P,
                     const float* __restrict__ L,
                     float* __restrict__ out) {
    // Z spectrum, lane-transposed: zbuf[lane*ZPAD + a] = Z[32a + lane].
    __shared__ alignas(16) float2 zbuf[32 * ZPAD];
    __shared__ alignas(16) float2 tb[4][32 * 32];

    const int b    = blockIdx.x;
    const int tid  = threadIdx.x;
    const int wid  = tid >> 5;
    const int lane = tid & 31;

    const float* pr = P + (size_t)b * HRR;
    const float* lr = L + (size_t)b * HRR;
    float* outr = out + (size_t)b * OUTW;

    ull v[32];

    if (wid == 0) {
        // Warp 0: forward FFT of z = p + i*l (runs concurrently with the copy)
#pragma unroll
        for (int a = 0; a < 32; a++)
            v[a] = pk(__ldg(&pr[32 * a + lane]), __ldg(&lr[32 * a + lane]));
        warp_fft1024<-1, false>(v, lane, tb[0]);
#pragma unroll
        for (int r = 0; r < 32; r++)
            *(ull*)&zbuf[lane * ZPAD + brev5(r)] = v[r];
    } else {
        // Warps 1-3: copy p, l rows into out[0:2048) (vectorized, streaming)
        const float4* p4 = (const float4*)pr;
        const float4* l4 = (const float4*)lr;
        float4* o4 = (float4*)outr;
        for (int i = tid - 32; i < HRR / 4; i += 96) {
            __stcs(&o4[i],           __ldg(&p4[i]));
            __stcs(&o4[HRR / 4 + i], __ldg(&l4[i]));
        }
    }
    __syncthreads();

    // 16 inverse FFTs, 4 per warp. Per FFT: 16 LDS.128 (z) + 16 LDG.128 (G);
    // output staged as re/im planes in tb, written by two 4KB bulk stores.
    float* tbf = (float*)tb[wid];                    // 2048 floats (8KB)
    const unsigned tbf_s = (unsigned)__cvta_generic_to_shared(tbf);
    const float4* z4 = (const float4*)(zbuf + lane * ZPAD);
#pragma unroll 1
    for (int d = wid; d < NDEC; d += 4) {
        const ulonglong2* Gw = g_Gw + (size_t)d * 16 * 32;
#pragma unroll
        for (int j = 0; j < 16; j++) {
            float4 zz = z4[j];                                  // a = 2j, 2j+1
            ulonglong2 g = __ldg(&Gw[j * 32 + lane]);
            float2 r0 = cmul(make_float2(zz.x, zz.y), unpk(g.x));
            float2 r1 = cmul(make_float2(zz.z, zz.w), unpk(g.y));
            v[2 * j]     = pk(r0.x, r0.y);
            v[2 * j + 1] = pk(r1.x, r1.y);
        }
        warp_fft1024<1, true>(v, lane, tb[wid]);   // waits prior bulk before tb reuse

        // Stage output planes: re -> tbf[0:1024), im -> tbf[1024:2048).
        // Per reg: lanes write one 128B row -> conflict-free STS.32.
#pragma unroll
        for (int r = 0; r < 32; r++) {
            int m = brev5(r);                       // k = lane + 32*m
            float2 s = unpk(v[r]);
            tbf[m * 32 + lane]        = s.x;
            tbf[1024 + m * 32 + lane] = s.y;
        }
        __syncwarp();
        if (lane == 0) {
            fence_async();
            bulk_store4k(outr + 2 * HRR + d * HRR,              tbf_s);
            bulk_store4k(outr + 2 * HRR + (NDEC + d) * HRR,     tbf_s + 4096);
            bulk_commit();
        }
    }
    if (lane == 0) bulk_wait0();   // drain before exit
}

// ---------------------------------------------------------------------------
extern "C" void kernel_launch(void* const* d_in, const int* in_sizes, int n_in,
                              void* d_out, int out_size) {
    // metadata order: problemhrr [B,1024], lemmahrr [B,1024], decoders [16,1024]
    const float* P = (const float*)d_in[0];
    const float* L = (const float*)d_in[1];
    const float* D = (const float*)d_in[2];
    // defensive: identify the decoders tensor by its unique size
    if (in_sizes[0] == NDEC * HRR) {
        D = (const float*)d_in[0]; P = (const float*)d_in[1]; L = (const float*)d_in[2];
    } else if (in_sizes[1] == NDEC * HRR) {
        P = (const float*)d_in[0]; D = (const float*)d_in[1]; L = (const float*)d_in[2];
    }
    const int B = out_size / OUTW;

    hrr_prep_kernel<<<NDEC, 32>>>(D);
    hrr_main_kernel<<<B, 128>>>(P, L, (float*)d_out);
}